// round 5
// baseline (speedup 1.0000x reference)
#include <cuda_runtime.h>
#include <math.h>
#include <stdint.h>

#define DIM 128

// Scratch: aggregation buffer [N, DIM] and sigmoid(rel) gate [R, DIM].
__device__ float g_agg[100000 * DIM];
__device__ float g_gate[500 * DIM];

__device__ __forceinline__ uint32_t smem_u32(const void* p) {
    uint32_t a;
    asm("{ .reg .u64 t; cvta.to.shared.u64 t, %1; cvt.u32.u64 %0, t; }"
        : "=r"(a) : "l"(p));
    return a;
}

__device__ __forceinline__ uint32_t f2tf32(float x) {
    uint32_t t;
    asm("cvt.rna.tf32.f32 %0, %1;" : "=r"(t) : "f"(x));
    return t;
}

#define CP_ASYNC(dst, src, sz) \
    asm volatile("cp.async.ca.shared.global [%0], [%1], 16, %2;" \
                 :: "r"(dst), "l"(src), "r"(sz) : "memory")
#define CP_COMMIT() asm volatile("cp.async.commit_group;" ::: "memory")
#define CP_WAIT(n)  asm volatile("cp.async.wait_group %0;" :: "n"(n) : "memory")

__device__ __forceinline__ void mma_tf32(float* c, const uint32_t* a,
                                         const uint32_t* b) {
    asm volatile(
        "mma.sync.aligned.m16n8k8.row.col.f32.tf32.tf32.f32 "
        "{%0,%1,%2,%3}, {%4,%5,%6,%7}, {%8,%9}, {%0,%1,%2,%3};"
        : "+f"(c[0]), "+f"(c[1]), "+f"(c[2]), "+f"(c[3])
        : "r"(a[0]), "r"(a[1]), "r"(a[2]), "r"(a[3]), "r"(b[0]), "r"(b[1]));
}

// ============================================================================
// SMEM layout for the 64x128 GEMM tile (pitch 36 floats, double buffered)
//   A: 64 x 36 x 4B x 2   = 18432
//   B: 128 x 36 x 4B x 2  = 36864
//   bias: 512
// ============================================================================
#define PITCH 36
#define SM_A(b)  ((b) * 9216)
#define SM_B(b)  (18432 + (b) * 18432)
#define SM_BIAS  55296
#define GEMM_SMEM 55808

// ============================================================================
// Kernel 1: prep — zero agg, gate = sigmoid(rel), out_rel = rel @ W_rel^T + b.
// Blocks [0,250): 2 relation rows each. Blocks [250, 250+ZB): zero agg.
// ============================================================================
#define ZB 1024
__global__ void prep_kernel(const float* __restrict__ rel,
                            const float* __restrict__ W_rel,
                            const float* __restrict__ b_rel,
                            float* __restrict__ out_rel,
                            int R, int n4) {
    int bid = blockIdx.x;
    int tid = threadIdx.x;
    if (bid < 250) {
        __shared__ float srow[2][DIM];
        int half = tid >> 7;          // 0 or 1
        int t = tid & 127;
        int r = 2 * bid + half;
        if (r < R) {
            float x = rel[r * DIM + t];
            srow[half][t] = x;
            g_gate[r * DIM + t] = 1.f / (1.f + expf(-x));
        }
        __syncthreads();
        if (r < R) {
            float acc = b_rel[t];
            const float4* w4 = (const float4*)&W_rel[t * DIM];
#pragma unroll
            for (int k4 = 0; k4 < DIM / 4; k4++) {
                float4 w = w4[k4];
                float4 xx = *(const float4*)&srow[half][k4 * 4];
                acc += w.x * xx.x + w.y * xx.y + w.z * xx.z + w.w * xx.w;
            }
            out_rel[r * DIM + t] = acc;
        }
    } else {
        int i = (bid - 250) * 256 + tid;
        float4 z = make_float4(0.f, 0.f, 0.f, 0.f);
        for (; i < n4; i += ZB * 256) ((float4*)g_agg)[i] = z;
    }
}

// ============================================================================
// GEMM tile worker: 64 rows x 128 cols, K=128 in 4 chunks of 32, double buffer.
// 8 warps in 2x4 grid, warp tile m32 x n32 (mma.m16n8k8 tf32).
// SELF: out = A@B^T + bias (no relu).  !SELF: out = relu(out + A@B^T).
// ============================================================================
template <bool SELF>
__device__ __forceinline__ void gemm_tile64(const float* __restrict__ A,
                                            const float* __restrict__ B,
                                            const float* __restrict__ bias_sum0,
                                            const float* __restrict__ bias_sum1,
                                            float* __restrict__ out,
                                            int tile, int N,
                                            char* smem, uint32_t sb) {
    int tid = threadIdx.x;
    int wid = tid >> 5;
    int lid = tid & 31;
    int wm = wid >> 2;            // 0-1
    int wn = wid & 3;             // 0-3
    int gid = lid >> 2;           // 0-7
    int tig = lid & 3;            // 0-3
    int row0 = tile * 64;

    float* biasS = (float*)(smem + SM_BIAS);
    if (SELF && tid < 128) biasS[tid] = bias_sum0[tid] + bias_sum1[tid];

    auto load_chunk = [&](int kc, int buf) {
        int akoff = kc * 32;
#pragma unroll
        for (int j = 0; j < 2; j++) {
            int idx = j * 256 + tid;
            int r = idx >> 3;
            int f4 = idx & 7;
            int arow = row0 + r;
            uint32_t ad = sb + SM_A(buf) + (uint32_t)(r * PITCH + f4 * 4) * 4;
            CP_ASYNC(ad, A + (size_t)arow * DIM + akoff + f4 * 4,
                     (arow < N) ? 16 : 0);
        }
#pragma unroll
        for (int j = 0; j < 4; j++) {
            int idx = j * 256 + tid;
            int r = idx >> 3;
            int f4 = idx & 7;
            uint32_t bd = sb + SM_B(buf) + (uint32_t)(r * PITCH + f4 * 4) * 4;
            CP_ASYNC(bd, B + (size_t)r * DIM + akoff + f4 * 4, 16);
        }
        CP_COMMIT();
    };

    load_chunk(0, 0);

    float acc[2][4][4];
#pragma unroll
    for (int mt = 0; mt < 2; mt++)
#pragma unroll
        for (int nt = 0; nt < 4; nt++)
#pragma unroll
            for (int j = 0; j < 4; j++) acc[mt][nt][j] = 0.f;

    for (int kc = 0; kc < 4; kc++) {
        int buf = kc & 1;
        if (kc < 3) load_chunk(kc + 1, buf ^ 1);
        if (kc < 3) { CP_WAIT(1); } else { CP_WAIT(0); }
        __syncthreads();

        const float* As = (const float*)(smem + SM_A(buf));
        const float* Bs = (const float*)(smem + SM_B(buf));

#pragma unroll
        for (int s = 0; s < 4; s++) {
            uint32_t a[2][4], b[4][2];
#pragma unroll
            for (int mt = 0; mt < 2; mt++) {
                int r = wm * 32 + mt * 16 + gid;
                int c = s * 8 + tig;
                a[mt][0] = f2tf32(As[r * PITCH + c]);
                a[mt][1] = f2tf32(As[(r + 8) * PITCH + c]);
                a[mt][2] = f2tf32(As[r * PITCH + c + 4]);
                a[mt][3] = f2tf32(As[(r + 8) * PITCH + c + 4]);
            }
#pragma unroll
            for (int nt = 0; nt < 4; nt++) {
                int n = wn * 32 + nt * 8 + gid;
                int k = s * 8 + tig;
                b[nt][0] = f2tf32(Bs[n * PITCH + k]);
                b[nt][1] = f2tf32(Bs[n * PITCH + k + 4]);
            }
#pragma unroll
            for (int mt = 0; mt < 2; mt++)
#pragma unroll
                for (int nt = 0; nt < 4; nt++)
                    mma_tf32(acc[mt][nt], a[mt], b[nt]);
        }
        __syncthreads();
    }

#pragma unroll
    for (int nt = 0; nt < 4; nt++) {
        int col = wn * 32 + nt * 8 + 2 * tig;
        float b0 = 0.f, b1 = 0.f;
        if (SELF) { b0 = biasS[col]; b1 = biasS[col + 1]; }
#pragma unroll
        for (int mt = 0; mt < 2; mt++) {
            int r1 = row0 + wm * 32 + mt * 16 + gid;
            int r2 = r1 + 8;
            float* d = acc[mt][nt];
            if (SELF) {
                if (r1 < N) {
                    float2 v = make_float2(d[0] + b0, d[1] + b1);
                    *(float2*)&out[(size_t)r1 * DIM + col] = v;
                }
                if (r2 < N) {
                    float2 v = make_float2(d[2] + b0, d[3] + b1);
                    *(float2*)&out[(size_t)r2 * DIM + col] = v;
                }
            } else {
                if (r1 < N) {
                    float2 p = *(const float2*)&out[(size_t)r1 * DIM + col];
                    float2 v = make_float2(fmaxf(p.x + d[0], 0.f),
                                           fmaxf(p.y + d[1], 0.f));
                    *(float2*)&out[(size_t)r1 * DIM + col] = v;
                }
                if (r2 < N) {
                    float2 p = *(const float2*)&out[(size_t)r2 * DIM + col];
                    float2 v = make_float2(fmaxf(p.x + d[2], 0.f),
                                           fmaxf(p.y + d[3], 0.f));
                    *(float2*)&out[(size_t)r2 * DIM + col] = v;
                }
            }
        }
    }
}

// ============================================================================
// Kernel 2: fused — self-GEMM (bid%4==0) + edge scatter (other blocks).
//   self:  out = ent @ W_self^T + (b_self + b_nei)   [fp32 partial, no relu]
//   edge:  g_agg[dst] += ent[src] * gate[etype]      [REDG.v4 per lane]
// ============================================================================
__global__ void __launch_bounds__(256, 3)
fused_kernel(const float* __restrict__ ent,
             const float* __restrict__ W_self,
             const float* __restrict__ b_self,
             const float* __restrict__ b_nei,
             const int* __restrict__ eidx,
             const int* __restrict__ etype,
             float* __restrict__ out,
             int N, int E) {
    extern __shared__ char smem[];
    int bid = blockIdx.x;

    if ((bid & 3) == 0) {
        uint32_t sb = smem_u32(smem);
        gemm_tile64<true>(ent, W_self, b_self, b_nei, out, bid >> 2, N,
                          smem, sb);
    } else {
        int erank = bid - (bid >> 2) - 1;
        int nedge_blocks = gridDim.x - ((gridDim.x + 3) >> 2);
        int wid = threadIdx.x >> 5;
        int lane = threadIdx.x & 31;
        int stride = nedge_blocks * 8;

        for (int e = erank * 8 + wid; e < E; e += stride) {
            int src = eidx[e];
            int dst = eidx[E + e];
            int t   = etype[e];

            float4 e4 = ((const float4*)ent)[src * 32 + lane];
            float4 g4 = ((const float4*)g_gate)[t * 32 + lane];
            float4 m;
            m.x = e4.x * g4.x;
            m.y = e4.y * g4.y;
            m.z = e4.z * g4.z;
            m.w = e4.w * g4.w;

            float* p = &g_agg[(size_t)dst * DIM + lane * 4];
            asm volatile("red.global.add.v4.f32 [%0], {%1, %2, %3, %4};"
                         :: "l"(p), "f"(m.x), "f"(m.y), "f"(m.z), "f"(m.w)
                         : "memory");
        }
    }
}

// ============================================================================
// Kernel 3: nei — out = relu(out + agg @ W_nei^T)
// ============================================================================
__global__ void __launch_bounds__(256, 3)
nei_kernel(const float* __restrict__ W_nei,
           float* __restrict__ out,
           int N) {
    extern __shared__ char smem[];
    uint32_t sb = smem_u32(smem);
    gemm_tile64<false>((const float*)g_agg, W_nei, nullptr, nullptr, out,
                       blockIdx.x, N, smem, sb);
}

// ============================================================================
// Launch. Inputs: ent, rel, edge_index(int32 [2,E]), edge_type(int32 [E]),
// W_self, b_self, W_nei, b_nei, W_rel, b_rel.
// Output: out_ent [N,128] then out_rel [R,128].
// ============================================================================
extern "C" void kernel_launch(void* const* d_in, const int* in_sizes, int n_in,
                              void* d_out, int out_size) {
    const float* ent    = (const float*)d_in[0];
    const float* rel    = (const float*)d_in[1];
    const int* eidx     = (const int*)d_in[2];
    const int* etype    = (const int*)d_in[3];
    const float* W_self = (const float*)d_in[4];
    const float* b_self = (const float*)d_in[5];
    const float* W_nei  = (const float*)d_in[6];
    const float* b_nei  = (const float*)d_in[7];
    const float* W_rel  = (const float*)d_in[8];
    const float* b_rel  = (const float*)d_in[9];

    int N = in_sizes[0] / DIM;   // 100000
    int R = in_sizes[1] / DIM;   // 500
    int E = in_sizes[3];         // 600000

    float* out_ent = (float*)d_out;
    float* out_rel = (float*)d_out + (size_t)N * DIM;

    static int smem_set = 0;
    if (!smem_set) {
        cudaFuncSetAttribute(fused_kernel,
                             cudaFuncAttributeMaxDynamicSharedMemorySize,
                             GEMM_SMEM);
        cudaFuncSetAttribute(nei_kernel,
                             cudaFuncAttributeMaxDynamicSharedMemorySize,
                             GEMM_SMEM);
        smem_set = 1;
    }

    int n4 = N * (DIM / 4);
    prep_kernel<<<250 + ZB, 256>>>(rel, W_rel, b_rel, out_rel, R, n4);

    int ntiles = (N + 63) / 64;          // 1563
    int fused_grid = ntiles * 4;         // 1 gemm block per 3 edge blocks
    fused_kernel<<<fused_grid, 256, GEMM_SMEM>>>(
        ent, W_self, b_self, b_nei, eidx, etype, out_ent, N, E);

    nei_kernel<<<ntiles, 256, GEMM_SMEM>>>(W_nei, out_ent, N);
}

// round 6
// speedup vs baseline: 1.8886x; 1.8886x over previous
#include <cuda_runtime.h>
#include <math.h>
#include <stdint.h>

#define DIM 128
#define NMAX 100000
#define MAXDEG 64

// Scratch buffers (static; no allocation allowed).
__device__ float g_agg[NMAX * DIM];          // aggregated messages [N,128]
__device__ float g_gate[500 * DIM];          // sigmoid(rel)
__device__ int   g_cursor[NMAX];             // per-dst bucket cursor
__device__ int2  g_slots[NMAX * MAXDEG];     // (src, type) per incident edge

__device__ __forceinline__ uint32_t smem_u32(const void* p) {
    uint32_t a;
    asm("{ .reg .u64 t; cvta.to.shared.u64 t, %1; cvt.u32.u64 %0, t; }"
        : "=r"(a) : "l"(p));
    return a;
}

__device__ __forceinline__ uint32_t f2tf32(float x) {
    uint32_t t;
    asm("cvt.rna.tf32.f32 %0, %1;" : "=r"(t) : "f"(x));
    return t;
}

#define CP_ASYNC(dst, src, sz) \
    asm volatile("cp.async.ca.shared.global [%0], [%1], 16, %2;" \
                 :: "r"(dst), "l"(src), "r"(sz) : "memory")
#define CP_COMMIT() asm volatile("cp.async.commit_group;" ::: "memory")
#define CP_WAIT(n)  asm volatile("cp.async.wait_group %0;" :: "n"(n) : "memory")

__device__ __forceinline__ void mma_tf32(float* c, const uint32_t* a,
                                         const uint32_t* b) {
    asm volatile(
        "mma.sync.aligned.m16n8k8.row.col.f32.tf32.tf32.f32 "
        "{%0,%1,%2,%3}, {%4,%5,%6,%7}, {%8,%9}, {%0,%1,%2,%3};"
        : "+f"(c[0]), "+f"(c[1]), "+f"(c[2]), "+f"(c[3])
        : "r"(a[0]), "r"(a[1]), "r"(a[2]), "r"(a[3]), "r"(b[0]), "r"(b[1]));
}

// ============================================================================
// Kernel 1: prep — zero cursor; gate = sigmoid(rel); out_rel = rel@W_rel^T + b.
// Blocks [0,250): 2 relation rows each. Blocks [250,250+ZC): zero cursor.
// ============================================================================
#define ZC 98
__global__ void prep_kernel(const float* __restrict__ rel,
                            const float* __restrict__ W_rel,
                            const float* __restrict__ b_rel,
                            float* __restrict__ out_rel,
                            int R, int N) {
    int bid = blockIdx.x;
    int tid = threadIdx.x;
    if (bid < 250) {
        __shared__ float srow[2][DIM];
        int half = tid >> 7;
        int t = tid & 127;
        int r = 2 * bid + half;
        if (r < R) {
            float x = rel[r * DIM + t];
            srow[half][t] = x;
            g_gate[r * DIM + t] = 1.f / (1.f + expf(-x));
        }
        __syncthreads();
        if (r < R) {
            float acc = b_rel[t];
            const float4* w4 = (const float4*)&W_rel[t * DIM];
#pragma unroll
            for (int k4 = 0; k4 < DIM / 4; k4++) {
                float4 w = w4[k4];
                float4 xx = *(const float4*)&srow[half][k4 * 4];
                acc += w.x * xx.x + w.y * xx.y + w.z * xx.z + w.w * xx.w;
            }
            out_rel[r * DIM + t] = acc;
        }
    } else {
        int n4 = (N + 3) >> 2;
        for (int i = (bid - 250) * 256 + tid; i < n4; i += ZC * 256)
            ((int4*)g_cursor)[i] = make_int4(0, 0, 0, 0);
    }
}

// ============================================================================
// Kernel 2: fill — bucket each edge under its destination.
// ============================================================================
__global__ void fill_kernel(const int* __restrict__ eidx,
                            const int* __restrict__ etype,
                            int E) {
    int e = blockIdx.x * blockDim.x + threadIdx.x;
    if (e >= E) return;
    int dst = eidx[E + e];
    int pos = atomicAdd(&g_cursor[dst], 1);
    if (pos < MAXDEG)
        g_slots[dst * MAXDEG + pos] = make_int2(eidx[e], etype[e]);
}

// ============================================================================
// Kernel 3: aggregate — warp per dst: sum ent[src]*gate[type] over its bucket,
// single non-atomic 512B row store. Unrolled by 2 for load-latency overlap.
// ============================================================================
__global__ void __launch_bounds__(256)
agg_kernel(const float* __restrict__ ent, int N) {
    int warp = (blockIdx.x * blockDim.x + threadIdx.x) >> 5;
    int lane = threadIdx.x & 31;
    if (warp >= N) return;

    int deg = g_cursor[warp];
    const int2* sl = &g_slots[warp * MAXDEG];

    float4 acc = make_float4(0.f, 0.f, 0.f, 0.f);
    int e = 0;
    for (; e + 2 <= deg; e += 2) {
        int2 s0 = sl[e];
        int2 s1 = sl[e + 1];
        float4 e0 = ((const float4*)ent)[s0.x * 32 + lane];
        float4 g0 = ((const float4*)g_gate)[s0.y * 32 + lane];
        float4 e1 = ((const float4*)ent)[s1.x * 32 + lane];
        float4 g1 = ((const float4*)g_gate)[s1.y * 32 + lane];
        acc.x += e0.x * g0.x + e1.x * g1.x;
        acc.y += e0.y * g0.y + e1.y * g1.y;
        acc.z += e0.z * g0.z + e1.z * g1.z;
        acc.w += e0.w * g0.w + e1.w * g1.w;
    }
    if (e < deg) {
        int2 s0 = sl[e];
        float4 e0 = ((const float4*)ent)[s0.x * 32 + lane];
        float4 g0 = ((const float4*)g_gate)[s0.y * 32 + lane];
        acc.x += e0.x * g0.x;
        acc.y += e0.y * g0.y;
        acc.z += e0.z * g0.z;
        acc.w += e0.w * g0.w;
    }
    ((float4*)g_agg)[warp * 32 + lane] = acc;
}

// ============================================================================
// Kernel 4: tf32 mma.sync GEMM (R4 design, unchanged)
//   out = relu( X @ Wc^T + bias ),  X = [ent | agg] (K=256), Wc = [W_self|W_nei]
// Block tile 128x128, K chunks of 32, cp.async double buffer.
// ============================================================================
#define PITCH 36
#define TILE_BYTES (128 * PITCH * 4)   // 18432
#define SM_AS(b)  ((b) * TILE_BYTES)
#define SM_BS(b)  (2 * TILE_BYTES + (b) * TILE_BYTES)
#define SM_BIAS   (4 * TILE_BYTES)
#define GEMM_SMEM (4 * TILE_BYTES + 512)

__global__ void __launch_bounds__(256, 2)
gemm_mma_kernel(const float* __restrict__ ent,
                const float* __restrict__ W_self,
                const float* __restrict__ b_self,
                const float* __restrict__ W_nei,
                const float* __restrict__ b_nei,
                float* __restrict__ out,
                int N) {
    extern __shared__ char smem[];
    uint32_t sb = smem_u32(smem);
    float* bias = (float*)(smem + SM_BIAS);

    int tid = threadIdx.x;
    int wid = tid >> 5;
    int lid = tid & 31;
    int wm = wid >> 2;
    int wn = wid & 3;
    int gid = lid >> 2;
    int tig = lid & 3;

    int row0 = blockIdx.x * 128;

    if (tid < 128) bias[tid] = b_self[tid] + b_nei[tid];

    auto load_chunk = [&](int kc, int buf) {
        const float* asrc = (kc < 4) ? ent : (const float*)g_agg;
        int akoff = (kc & 3) * 32;
        const float* bsrc = (kc < 4) ? W_self : W_nei;
#pragma unroll
        for (int j = 0; j < 4; j++) {
            int idx = j * 256 + tid;
            int r = idx >> 3;
            int f4 = idx & 7;
            int arow = row0 + r;
            uint32_t ad = sb + SM_AS(buf) + (uint32_t)(r * PITCH + f4 * 4) * 4;
            const float* ag = asrc + (size_t)arow * DIM + akoff + f4 * 4;
            CP_ASYNC(ad, ag, (arow < N) ? 16 : 0);
            uint32_t bd = sb + SM_BS(buf) + (uint32_t)(r * PITCH + f4 * 4) * 4;
            const float* bg = bsrc + (size_t)r * DIM + akoff + f4 * 4;
            CP_ASYNC(bd, bg, 16);
        }
        CP_COMMIT();
    };

    load_chunk(0, 0);

    float acc[4][4][4];
#pragma unroll
    for (int mt = 0; mt < 4; mt++)
#pragma unroll
        for (int nt = 0; nt < 4; nt++)
#pragma unroll
            for (int j = 0; j < 4; j++) acc[mt][nt][j] = 0.f;

    for (int kc = 0; kc < 8; kc++) {
        int buf = kc & 1;
        if (kc < 7) load_chunk(kc + 1, buf ^ 1);
        if (kc < 7) { CP_WAIT(1); } else { CP_WAIT(0); }
        __syncthreads();

        const float* As = (const float*)(smem + SM_AS(buf));
        const float* Bs = (const float*)(smem + SM_BS(buf));

#pragma unroll
        for (int s = 0; s < 4; s++) {
            uint32_t a[4][4], b[4][2];
#pragma unroll
            for (int mt = 0; mt < 4; mt++) {
                int r = wm * 64 + mt * 16 + gid;
                int c = s * 8 + tig;
                a[mt][0] = f2tf32(As[r * PITCH + c]);
                a[mt][1] = f2tf32(As[(r + 8) * PITCH + c]);
                a[mt][2] = f2tf32(As[r * PITCH + c + 4]);
                a[mt][3] = f2tf32(As[(r + 8) * PITCH + c + 4]);
            }
#pragma unroll
            for (int nt = 0; nt < 4; nt++) {
                int n = wn * 32 + nt * 8 + gid;
                int k = s * 8 + tig;
                b[nt][0] = f2tf32(Bs[n * PITCH + k]);
                b[nt][1] = f2tf32(Bs[n * PITCH + k + 4]);
            }
#pragma unroll
            for (int mt = 0; mt < 4; mt++)
#pragma unroll
                for (int nt = 0; nt < 4; nt++)
                    mma_tf32(acc[mt][nt], a[mt], b[nt]);
        }
        __syncthreads();
    }

#pragma unroll
    for (int nt = 0; nt < 4; nt++) {
        int col = wn * 32 + nt * 8 + 2 * tig;
        float b0 = bias[col], b1 = bias[col + 1];
#pragma unroll
        for (int mt = 0; mt < 4; mt++) {
            int r1 = row0 + wm * 64 + mt * 16 + gid;
            int r2 = r1 + 8;
            float* d = acc[mt][nt];
            if (r1 < N) {
                float2 v = make_float2(fmaxf(d[0] + b0, 0.f),
                                       fmaxf(d[1] + b1, 0.f));
                *(float2*)&out[(size_t)r1 * DIM + col] = v;
            }
            if (r2 < N) {
                float2 v = make_float2(fmaxf(d[2] + b0, 0.f),
                                       fmaxf(d[3] + b1, 0.f));
                *(float2*)&out[(size_t)r2 * DIM + col] = v;
            }
        }
    }
}

// ============================================================================
// Launch. Inputs: ent, rel, edge_index(int32 [2,E]), edge_type(int32 [E]),
// W_self, b_self, W_nei, b_nei, W_rel, b_rel.
// Output: out_ent [N,128] then out_rel [R,128].
// ============================================================================
extern "C" void kernel_launch(void* const* d_in, const int* in_sizes, int n_in,
                              void* d_out, int out_size) {
    const float* ent    = (const float*)d_in[0];
    const float* rel    = (const float*)d_in[1];
    const int* eidx     = (const int*)d_in[2];
    const int* etype    = (const int*)d_in[3];
    const float* W_self = (const float*)d_in[4];
    const float* b_self = (const float*)d_in[5];
    const float* W_nei  = (const float*)d_in[6];
    const float* b_nei  = (const float*)d_in[7];
    const float* W_rel  = (const float*)d_in[8];
    const float* b_rel  = (const float*)d_in[9];

    int N = in_sizes[0] / DIM;   // 100000
    int R = in_sizes[1] / DIM;   // 500
    int E = in_sizes[3];         // 600000

    float* out_ent = (float*)d_out;
    float* out_rel = (float*)d_out + (size_t)N * DIM;

    static int smem_set = 0;
    if (!smem_set) {
        cudaFuncSetAttribute(gemm_mma_kernel,
                             cudaFuncAttributeMaxDynamicSharedMemorySize,
                             GEMM_SMEM);
        smem_set = 1;
    }

    prep_kernel<<<250 + ZC, 256>>>(rel, W_rel, b_rel, out_rel, R, N);

    fill_kernel<<<(E + 255) / 256, 256>>>(eidx, etype, E);

    agg_kernel<<<(N * 32 + 255) / 256, 256>>>(ent, N);

    int gemm_blocks = (N + 127) / 128;
    gemm_mma_kernel<<<gemm_blocks, 256, GEMM_SMEM>>>(
        ent, W_self, b_self, W_nei, b_nei, out_ent, N);
}